// round 4
// baseline (speedup 1.0000x reference)
#include <cuda_runtime.h>

// ---------------- scratch (device globals, no runtime allocation) ----------
__device__ float g_h1p[1024 * 32 * 196];     // stage-1 output, pooled (b,c,p14)
__device__ float g_h2 [1024 * 64 * 196];     // stage-2 output (b,c,p14) == flatten layout
__device__ float g_w2r [9 * 32 * 64];        // w2 reordered [k][c][co]
__device__ float g_ow2r[9 * 32 * 20];        // ow2 reordered [k][c][o(pad20)]
__device__ float g_fw1T[12544 * 128];        // fw1 transposed [k][n]
__device__ float g_fc1part[8 * 1024 * 128];  // split-K partials
__device__ float g_h3 [1024 * 128];          // fc1 output

// ---------------- prep kernels --------------------------------------------
__global__ void prep_w2r(const float* __restrict__ w2) {
    int id = blockIdx.x * blockDim.x + threadIdx.x;       // 9*32*64 = 18432
    if (id >= 9 * 32 * 64) return;
    int co = id % 64; int c = (id / 64) % 32; int k = id / (64 * 32);
    g_w2r[(k * 32 + c) * 64 + co] = w2[(co * 32 + c) * 9 + k];
}

__global__ void prep_ow2r(const float* __restrict__ ow2) {
    int id = blockIdx.x * blockDim.x + threadIdx.x;       // 9*32*20 = 5760
    if (id >= 9 * 32 * 20) return;
    int o = id % 20; int c = (id / 20) % 32; int k = id / (20 * 32);
    g_ow2r[(k * 32 + c) * 20 + o] = (o < 18) ? ow2[(o * 32 + c) * 9 + k] : 0.0f;
}

__global__ void prep_fw1T(const float* __restrict__ fw1) {
    int id = blockIdx.x * blockDim.x + threadIdx.x;       // 12544*128
    if (id >= 12544 * 128) return;
    int n = id % 128; int k = id / 128;
    g_fw1T[id] = fw1[n * 12544 + k];
}

// ---------------- stage 1: conv1(offsets) + deform1 + relu + pool2x2 ------
__device__ __forceinline__ float samp28(const float* sx, int y, int x) {
    return (y >= 0 && y < 28 && x >= 0 && x < 28) ? sx[y * 28 + x] : 0.0f;
}

__global__ __launch_bounds__(196) void kA(
    const float* __restrict__ x,  const float* __restrict__ ow1,
    const float* __restrict__ ob1, const float* __restrict__ w1,
    const float* __restrict__ b1)
{
    __shared__ float sx[784];
    __shared__ float sow1[162], sob1[18], sw1[288], sb1[32];
    int b = blockIdx.x, t = threadIdx.x;
    for (int i = t; i < 784; i += 196) sx[i] = x[b * 784 + i];
    for (int i = t; i < 162; i += 196) sow1[i] = ow1[i];
    for (int i = t; i < 288; i += 196) sw1[i] = w1[i];
    if (t < 18) sob1[t] = ob1[t];
    if (t < 32) sb1[t] = b1[t];
    __syncthreads();

    int oy = t / 14, ox = t % 14;
    float pool[32];
#pragma unroll
    for (int c = 0; c < 32; c++) pool[c] = 0.0f;

#pragma unroll
    for (int sub = 0; sub < 4; sub++) {
        int y = oy * 2 + (sub >> 1);
        int xx0 = ox * 2 + (sub & 1);

        // offset conv (1->18), 3x3, pad 1
        float off[18];
#pragma unroll
        for (int o = 0; o < 18; o++) off[o] = sob1[o];
#pragma unroll
        for (int ky = 0; ky < 3; ky++)
#pragma unroll
            for (int kx = 0; kx < 3; kx++) {
                int yy = y - 1 + ky, xc = xx0 - 1 + kx;
                float xv = samp28(sx, yy, xc);
#pragma unroll
                for (int o = 0; o < 18; o++) off[o] += sow1[o * 9 + ky * 3 + kx] * xv;
            }

        // deformable bilinear sampling, Cin=1
        float s[9];
#pragma unroll
        for (int k = 0; k < 9; k++) {
            float py = off[2 * k]     + (float)(y  - 1 + k / 3);
            float px = off[2 * k + 1] + (float)(xx0 - 1 + k % 3);
            float y0f = floorf(py), x0f = floorf(px);
            int y0 = (int)y0f, x0i = (int)x0f;
            float wy1 = py - y0f, wx1 = px - x0f;
            float wy0 = 1.0f - wy1, wx0 = 1.0f - wx1;
            float v00 = samp28(sx, y0,     x0i    );
            float v01 = samp28(sx, y0,     x0i + 1);
            float v10 = samp28(sx, y0 + 1, x0i    );
            float v11 = samp28(sx, y0 + 1, x0i + 1);
            s[k] = v00 * wy0 * wx0 + v01 * wy0 * wx1 + v10 * wy1 * wx0 + v11 * wy1 * wx1;
        }

#pragma unroll
        for (int c = 0; c < 32; c++) {
            float o = sb1[c];
#pragma unroll
            for (int k = 0; k < 9; k++) o += sw1[c * 9 + k] * s[k];
            pool[c] += fmaxf(o, 0.0f);
        }
    }
#pragma unroll
    for (int c = 0; c < 32; c++)
        g_h1p[(b * 32 + c) * 196 + t] = pool[c] * 0.25f;
}

// ---------------- stage 2: conv2(offsets) + deform2 + relu -----------------
__global__ __launch_bounds__(196) void kB(
    const float* __restrict__ ob2, const float* __restrict__ b2)
{
    __shared__ float sh[32 * 196];   // per-image activations [c][p]
    __shared__ float sob2[18], sb2[64];
    int b = blockIdx.x, t = threadIdx.x;
    for (int i = t; i < 32 * 196; i += 196) sh[i] = g_h1p[b * 6272 + i];
    if (t < 18) sob2[t] = ob2[t];
    if (t < 64) sb2[t] = b2[t];
    __syncthreads();

    int y = t / 14, x = t % 14;

    // offset conv (32->18), 3x3, pad 1
    float off[18];
#pragma unroll
    for (int o = 0; o < 18; o++) off[o] = sob2[o];
#pragma unroll
    for (int ky = 0; ky < 3; ky++)
#pragma unroll
        for (int kx = 0; kx < 3; kx++) {
            int yy = y - 1 + ky, xc = x - 1 + kx;
            if (yy >= 0 && yy < 14 && xc >= 0 && xc < 14) {
                int p2 = yy * 14 + xc;
                int kk = ky * 3 + kx;
#pragma unroll
                for (int c = 0; c < 32; c++) {
                    float hv = sh[c * 196 + p2];
                    const float4* w4 = reinterpret_cast<const float4*>(&g_ow2r[(kk * 32 + c) * 20]);
                    float4 a0 = w4[0], a1 = w4[1], a2 = w4[2], a3 = w4[3], a4 = w4[4];
                    off[0]  += a0.x * hv; off[1]  += a0.y * hv; off[2]  += a0.z * hv; off[3]  += a0.w * hv;
                    off[4]  += a1.x * hv; off[5]  += a1.y * hv; off[6]  += a1.z * hv; off[7]  += a1.w * hv;
                    off[8]  += a2.x * hv; off[9]  += a2.y * hv; off[10] += a2.z * hv; off[11] += a2.w * hv;
                    off[12] += a3.x * hv; off[13] += a3.y * hv; off[14] += a3.z * hv; off[15] += a3.w * hv;
                    off[16] += a4.x * hv; off[17] += a4.y * hv;
                }
            }
        }

    // deformable conv (32->64)
    float acc[64];
#pragma unroll
    for (int co = 0; co < 64; co++) acc[co] = sb2[co];

#pragma unroll
    for (int k = 0; k < 9; k++) {
        float py = off[2 * k]     + (float)(y - 1 + k / 3);
        float px = off[2 * k + 1] + (float)(x - 1 + k % 3);
        float y0f = floorf(py), x0f = floorf(px);
        int y0 = (int)y0f, x0i = (int)x0f;
        float wy1 = py - y0f, wx1 = px - x0f;
        float wy0 = 1.0f - wy1, wx0 = 1.0f - wx1;

        bool v00 = (y0 >= 0 && y0 < 14 && x0i     >= 0 && x0i     < 14);
        bool v01 = (y0 >= 0 && y0 < 14 && x0i + 1 >= 0 && x0i + 1 < 14);
        bool v10 = (y0 + 1 >= 0 && y0 + 1 < 14 && x0i     >= 0 && x0i     < 14);
        bool v11 = (y0 + 1 >= 0 && y0 + 1 < 14 && x0i + 1 >= 0 && x0i + 1 < 14);
        float c00 = v00 ? wy0 * wx0 : 0.0f; int i00 = v00 ? (y0 * 14 + x0i)           : 0;
        float c01 = v01 ? wy0 * wx1 : 0.0f; int i01 = v01 ? (y0 * 14 + x0i + 1)       : 0;
        float c10 = v10 ? wy1 * wx0 : 0.0f; int i10 = v10 ? ((y0 + 1) * 14 + x0i)     : 0;
        float c11 = v11 ? wy1 * wx1 : 0.0f; int i11 = v11 ? ((y0 + 1) * 14 + x0i + 1) : 0;

#pragma unroll
        for (int c = 0; c < 32; c++) {
            const float* shc = sh + c * 196;
            float v = c00 * shc[i00] + c01 * shc[i01] + c10 * shc[i10] + c11 * shc[i11];
            const float4* w4 = reinterpret_cast<const float4*>(&g_w2r[(k * 32 + c) * 64]);
#pragma unroll
            for (int j = 0; j < 16; j++) {
                float4 wv = w4[j];
                acc[j * 4 + 0] += v * wv.x;
                acc[j * 4 + 1] += v * wv.y;
                acc[j * 4 + 2] += v * wv.z;
                acc[j * 4 + 3] += v * wv.w;
            }
        }
    }
#pragma unroll
    for (int co = 0; co < 64; co++)
        g_h2[(b * 64 + co) * 196 + t] = fmaxf(acc[co], 0.0f);
}

// ---------------- FC1: split-K GEMM (M=1024, N=128, K=12544) ---------------
// BM=32, BN=128, BK=16, splitK=8, 256 threads/block, thread tile 4x4.
__global__ __launch_bounds__(256) void kC_gemm() {
    __shared__ float As[16][32];
    __shared__ float Bs[16][128];
    int tid = threadIdx.x;
    int m0 = blockIdx.x * 32;
    int z  = blockIdx.z;
    int kbase = z * 1568;

    float acc[16];
#pragma unroll
    for (int i = 0; i < 16; i++) acc[i] = 0.0f;

    int lm = tid / 8;            // A load: row within tile
    int lk = (tid % 8) * 2;      // A load: k pair
    int br = tid / 32;           // B load: row 0..7 (and +8)
    int bc = (tid % 32) * 4;     // B load: col quad

    int m_base = (tid >> 5) * 4;
    int n_base = (tid & 31) * 4;

    for (int it = 0; it < 98; it++) {
        int k0 = kbase + it * 16;
        // load A (32x16), store transposed As[k][m]
        const float* arow = g_h2 + (m0 + lm) * 12544 + k0 + lk;
        float a0 = arow[0], a1 = arow[1];
        As[lk][lm] = a0; As[lk + 1][lm] = a1;
        // load B (16x128)
        float4 b0 = *reinterpret_cast<const float4*>(&g_fw1T[(k0 + br) * 128 + bc]);
        float4 b1 = *reinterpret_cast<const float4*>(&g_fw1T[(k0 + br + 8) * 128 + bc]);
        *reinterpret_cast<float4*>(&Bs[br][bc]) = b0;
        *reinterpret_cast<float4*>(&Bs[br + 8][bc]) = b1;
        __syncthreads();
#pragma unroll
        for (int k = 0; k < 16; k++) {
            float4 av = *reinterpret_cast<const float4*>(&As[k][m_base]);
            float4 bv = *reinterpret_cast<const float4*>(&Bs[k][n_base]);
            acc[0]  += av.x * bv.x; acc[1]  += av.x * bv.y; acc[2]  += av.x * bv.z; acc[3]  += av.x * bv.w;
            acc[4]  += av.y * bv.x; acc[5]  += av.y * bv.y; acc[6]  += av.y * bv.z; acc[7]  += av.y * bv.w;
            acc[8]  += av.z * bv.x; acc[9]  += av.z * bv.y; acc[10] += av.z * bv.z; acc[11] += av.z * bv.w;
            acc[12] += av.w * bv.x; acc[13] += av.w * bv.y; acc[14] += av.w * bv.z; acc[15] += av.w * bv.w;
        }
        __syncthreads();
    }
#pragma unroll
    for (int i = 0; i < 4; i++)
#pragma unroll
        for (int j = 0; j < 4; j++)
            g_fc1part[z * 131072 + (m0 + m_base + i) * 128 + n_base + j] = acc[i * 4 + j];
}

__global__ void kE_reduce(const float* __restrict__ fb1) {
    int id = blockIdx.x * blockDim.x + threadIdx.x;  // 131072
    if (id >= 131072) return;
    int n = id % 128;
    float s = fb1[n];
#pragma unroll
    for (int zz = 0; zz < 8; zz++) s += g_fc1part[zz * 131072 + id];
    g_h3[id] = fmaxf(s, 0.0f);
}

// ---------------- FC2 ------------------------------------------------------
__global__ void kF_fc2(const float* __restrict__ fw2, const float* __restrict__ fb2,
                       float* __restrict__ out) {
    int id = blockIdx.x * blockDim.x + threadIdx.x;  // 10240
    if (id >= 10240) return;
    int m = id / 10, n = id % 10;
    float s = fb2[n];
    const float* hrow = g_h3 + m * 128;
    const float* wrow = fw2 + n * 128;
#pragma unroll 8
    for (int j = 0; j < 128; j++) s += hrow[j] * wrow[j];
    out[id] = s;
}

// ---------------- launch ---------------------------------------------------
extern "C" void kernel_launch(void* const* d_in, const int* in_sizes, int n_in,
                              void* d_out, int out_size) {
    const float* x   = (const float*)d_in[0];
    const float* ow1 = (const float*)d_in[1];
    const float* ob1 = (const float*)d_in[2];
    const float* w1  = (const float*)d_in[3];
    const float* b1  = (const float*)d_in[4];
    const float* ow2 = (const float*)d_in[5];
    const float* ob2 = (const float*)d_in[6];
    const float* w2  = (const float*)d_in[7];
    const float* b2  = (const float*)d_in[8];
    const float* fw1 = (const float*)d_in[9];
    const float* fb1 = (const float*)d_in[10];
    const float* fw2 = (const float*)d_in[11];
    const float* fb2 = (const float*)d_in[12];
    float* out = (float*)d_out;

    prep_w2r <<<(18432 + 255) / 256, 256>>>(w2);
    prep_ow2r<<<(5760  + 255) / 256, 256>>>(ow2);
    prep_fw1T<<<(12544 * 128 + 255) / 256, 256>>>(fw1);

    kA<<<1024, 196>>>(x, ow1, ob1, w1, b1);
    kB<<<1024, 196>>>(ob2, b2);

    dim3 gg(32, 1, 8);
    kC_gemm<<<gg, 256>>>();
    kE_reduce<<<(131072 + 255) / 256, 256>>>(fb1);
    kF_fc2<<<(10240 + 255) / 256, 256>>>(fw2, fb2, out);
}

// round 6
// speedup vs baseline: 1.9955x; 1.9955x over previous
#include <cuda_runtime.h>

typedef unsigned long long ull;

// ---------------- packed f32x2 helpers (sm_103a FFMA2 path) ----------------
__device__ __forceinline__ ull f2pack(float lo, float hi) {
    ull r; asm("mov.b64 %0,{%1,%2};" : "=l"(r) : "f"(lo), "f"(hi)); return r;
}
__device__ __forceinline__ ull splat2(float v) { return f2pack(v, v); }
__device__ __forceinline__ ull ffma2(ull a, ull b, ull c) {
    ull d; asm("fma.rn.f32x2 %0,%1,%2,%3;" : "=l"(d) : "l"(a), "l"(b), "l"(c)); return d;
}
__device__ __forceinline__ float2 f2unpack(ull v) {
    float2 r; asm("mov.b64 {%0,%1},%2;" : "=f"(r.x), "=f"(r.y) : "l"(v)); return r;
}

// ---------------- scratch (device globals, no runtime allocation) ----------
__device__ float g_h1p[1024 * 32 * 196];      // stage-1 output, pooled (b,c,p14)
__device__ float g_h2 [1024 * 64 * 196];      // stage-2 output (b,c,p14) == flatten layout
__device__ float g_w2r [9 * 32 * 64];         // w2 reordered [k][c][co]
__device__ float g_ow2r[9 * 32 * 20];         // ow2 reordered [k][c][o(pad20)]
__device__ float g_fw1T[12544 * 128];         // fw1 transposed [k][n]
__device__ float g_fc1part[16 * 1024 * 128];  // split-K partials
__device__ float g_h3 [1024 * 128];           // fc1 output

// ---------------- prep kernels --------------------------------------------
__global__ void prep_w2r(const float* __restrict__ w2) {
    int id = blockIdx.x * blockDim.x + threadIdx.x;       // 9*32*64 = 18432
    if (id >= 9 * 32 * 64) return;
    int co = id % 64; int c = (id / 64) % 32; int k = id / (64 * 32);
    g_w2r[(k * 32 + c) * 64 + co] = w2[(co * 32 + c) * 9 + k];
}

__global__ void prep_ow2r(const float* __restrict__ ow2) {
    int id = blockIdx.x * blockDim.x + threadIdx.x;       // 9*32*20 = 5760
    if (id >= 9 * 32 * 20) return;
    int o = id % 20; int c = (id / 20) % 32; int k = id / (20 * 32);
    g_ow2r[(k * 32 + c) * 20 + o] = (o < 18) ? ow2[(o * 32 + c) * 9 + k] : 0.0f;
}

__global__ void prep_fw1T(const float* __restrict__ fw1) {
    int id = blockIdx.x * blockDim.x + threadIdx.x;       // 12544*128
    if (id >= 12544 * 128) return;
    int n = id % 128; int k = id / 128;
    g_fw1T[id] = fw1[n * 12544 + k];
}

// ---------------- stage 1: conv1(offsets) + deform1 + relu + pool2x2 ------
__device__ __forceinline__ float samp28(const float* sx, int y, int x) {
    return (y >= 0 && y < 28 && x >= 0 && x < 28) ? sx[y * 28 + x] : 0.0f;
}

__global__ __launch_bounds__(784) void kA(
    const float* __restrict__ x,  const float* __restrict__ ow1,
    const float* __restrict__ ob1, const float* __restrict__ w1,
    const float* __restrict__ b1)
{
    __shared__ __align__(16) float sx[784];
    __shared__ __align__(16) float ss[9 * 784];    // bilinear samples [k][p28]
    __shared__ __align__(16) float sow1T[162];     // [k][o]
    __shared__ __align__(16) float sw1T[288];      // [k][c]
    __shared__ __align__(16) float sob1[18];
    __shared__ __align__(16) float sb1[32];
    int b = blockIdx.x, t = threadIdx.x;

    sx[t] = x[b * 784 + t];
    if (t < 162) { int o = t % 18, k = t / 18; sow1T[t] = ow1[o * 9 + k]; }
    if (t < 288) { int c = t % 32, k = t / 32; sw1T[t] = w1[c * 9 + k]; }
    if (t < 18) sob1[t] = ob1[t];
    if (t < 32) sb1[t] = b1[t];
    __syncthreads();

    // phase 1: one thread per 28x28 pixel — offset conv (1->18) + bilinear
    {
        int y = t / 28, xx = t % 28;
        ull off9[9];
        const ull* bb = (const ull*)sob1;
#pragma unroll
        for (int j = 0; j < 9; j++) off9[j] = bb[j];
#pragma unroll
        for (int ky = 0; ky < 3; ky++)
#pragma unroll
            for (int kx = 0; kx < 3; kx++) {
                float xv = samp28(sx, y - 1 + ky, xx - 1 + kx);
                ull xs = splat2(xv);
                const ull* wp = (const ull*)sow1T + (ky * 3 + kx) * 9;
#pragma unroll
                for (int j = 0; j < 9; j++) off9[j] = ffma2(xs, wp[j], off9[j]);
            }
#pragma unroll
        for (int k = 0; k < 9; k++) {
            float2 d = f2unpack(off9[k]);
            float py = d.x + (float)(y  - 1 + k / 3);
            float px = d.y + (float)(xx - 1 + k % 3);
            float y0f = floorf(py), x0f = floorf(px);
            int y0 = (int)y0f, x0i = (int)x0f;
            float wy1 = py - y0f, wx1 = px - x0f;
            float wy0 = 1.0f - wy1, wx0 = 1.0f - wx1;
            float v00 = samp28(sx, y0,     x0i    );
            float v01 = samp28(sx, y0,     x0i + 1);
            float v10 = samp28(sx, y0 + 1, x0i    );
            float v11 = samp28(sx, y0 + 1, x0i + 1);
            ss[k * 784 + t] = v00 * wy0 * wx0 + v01 * wy0 * wx1
                            + v10 * wy1 * wx0 + v11 * wy1 * wx1;
        }
    }
    __syncthreads();

    // phase 2: 4 groups x 8 channels, relu + 2x2 pool
    {
        int p = t % 196, g = t / 196;
        int oy = p / 14, ox = p % 14;
        float pool[8];
#pragma unroll
        for (int j = 0; j < 8; j++) pool[j] = 0.0f;
        const ull* bp = (const ull*)(sb1 + g * 8);
#pragma unroll
        for (int sub = 0; sub < 4; sub++) {
            int yy = oy * 2 + (sub >> 1);
            int xx = ox * 2 + (sub & 1);
            int pp = yy * 28 + xx;
            ull o4[4];
#pragma unroll
            for (int j = 0; j < 4; j++) o4[j] = bp[j];
#pragma unroll
            for (int k = 0; k < 9; k++) {
                ull vs = splat2(ss[k * 784 + pp]);
                const ull* wp = (const ull*)sw1T + k * 16 + g * 4;
                o4[0] = ffma2(vs, wp[0], o4[0]);
                o4[1] = ffma2(vs, wp[1], o4[1]);
                o4[2] = ffma2(vs, wp[2], o4[2]);
                o4[3] = ffma2(vs, wp[3], o4[3]);
            }
#pragma unroll
            for (int j = 0; j < 4; j++) {
                float2 u = f2unpack(o4[j]);
                pool[2 * j]     += fmaxf(u.x, 0.0f);
                pool[2 * j + 1] += fmaxf(u.y, 0.0f);
            }
        }
#pragma unroll
        for (int j = 0; j < 8; j++)
            g_h1p[(b * 32 + g * 8 + j) * 196 + p] = pool[j] * 0.25f;
    }
}

// ---------------- stage 2: conv2(offsets) + deform2 + relu -----------------
// 784 threads: 4 groups x (16 output channels | 8 input-channel slice).
// dynamic smem: sh[6272] | sv[6272] (ow2r, then gather buffer) | sw2[18432] | sbuf[14112]
__global__ __launch_bounds__(784) void kB(
    const float* __restrict__ ob2, const float* __restrict__ b2)
{
    extern __shared__ float smem[];
    float*    sh   = smem;            // 32*196 activations [c][p]
    float*    sv   = smem + 6272;     // ow2r (phase 2), gather v[c][p] (phase 4)
    float*    sw2  = smem + 12544;    // w2r [k][c][co]
    float*    sbuf = smem + 30976;    // offset partials -> coefs
    unsigned* sidx = (unsigned*)(smem + 30976) + 7056;  // packed tap indices
    __shared__ __align__(16) float sob2s[18];
    __shared__ __align__(16) float sb2s[64];

    int b = blockIdx.x, t = threadIdx.x;
    for (int i = t; i < 6272;  i += 784) sh[i]  = g_h1p[b * 6272 + i];
    for (int i = t; i < 5760;  i += 784) sv[i]  = g_ow2r[i];
    for (int i = t; i < 18432; i += 784) sw2[i] = g_w2r[i];
    if (t < 18) sob2s[t] = ob2[t];
    if (t < 64) sb2s[t]  = b2[t];
    __syncthreads();

    int g = t / 196, p = t % 196;
    int y = p / 14,  x = p % 14;

    // phase 2: partial offset conv (each group covers 8 input channels)
    {
        ull a9[9];
        if (g == 0) {
            const ull* bb = (const ull*)sob2s;
#pragma unroll
            for (int j = 0; j < 9; j++) a9[j] = bb[j];
        } else {
#pragma unroll
            for (int j = 0; j < 9; j++) a9[j] = 0ull;
        }
#pragma unroll
        for (int ky = 0; ky < 3; ky++)
#pragma unroll
            for (int kx = 0; kx < 3; kx++) {
                int yy = y - 1 + ky, xc = x - 1 + kx;
                if (yy >= 0 && yy < 14 && xc >= 0 && xc < 14) {
                    int p2 = yy * 14 + xc, kk = ky * 3 + kx;
                    const float* shb = sh + g * 8 * 196 + p2;
                    const ull* ow = (const ull*)sv + (kk * 32 + g * 8) * 10;
#pragma unroll
                    for (int cj = 0; cj < 8; cj++) {
                        ull hs = splat2(shb[cj * 196]);
                        const ull* wp = ow + cj * 10;
#pragma unroll
                        for (int j = 0; j < 9; j++) a9[j] = ffma2(hs, wp[j], a9[j]);
                    }
                }
            }
        float* dst = sbuf + (g * 196 + p) * 18;
#pragma unroll
        for (int j = 0; j < 9; j++) {
            float2 u = f2unpack(a9[j]);
            dst[2 * j] = u.x; dst[2 * j + 1] = u.y;
        }
    }
    __syncthreads();

    // phase 3: reduce partials, compute bilinear coefs + packed indices
    float offv[18];
    if (t < 196) {
#pragma unroll
        for (int o = 0; o < 18; o++)
            offv[o] = sbuf[t * 18 + o] + sbuf[(196 + t) * 18 + o]
                    + sbuf[(392 + t) * 18 + o] + sbuf[(588 + t) * 18 + o];
    }
    __syncthreads();
    if (t < 196) {
#pragma unroll
        for (int k = 0; k < 9; k++) {
            float py = offv[2 * k]     + (float)(y - 1 + k / 3);
            float px = offv[2 * k + 1] + (float)(x - 1 + k % 3);
            float y0f = floorf(py), x0f = floorf(px);
            int y0 = (int)y0f, x0i = (int)x0f;
            float wy1 = py - y0f, wx1 = px - x0f;
            float wy0 = 1.0f - wy1, wx0 = 1.0f - wx1;
            bool by0 = (y0 >= 0) && (y0 < 14);
            bool by1 = (y0 + 1 >= 0) && (y0 + 1 < 14);
            bool bx0 = (x0i >= 0) && (x0i < 14);
            bool bx1 = (x0i + 1 >= 0) && (x0i + 1 < 14);
            float c00 = (by0 && bx0) ? wy0 * wx0 : 0.0f;
            float c01 = (by0 && bx1) ? wy0 * wx1 : 0.0f;
            float c10 = (by1 && bx0) ? wy1 * wx0 : 0.0f;
            float c11 = (by1 && bx1) ? wy1 * wx1 : 0.0f;
            unsigned i00 = (by0 && bx0) ? (unsigned)(y0 * 14 + x0i)           : 0u;
            unsigned i01 = (by0 && bx1) ? (unsigned)(y0 * 14 + x0i + 1)       : 0u;
            unsigned i10 = (by1 && bx0) ? (unsigned)((y0 + 1) * 14 + x0i)     : 0u;
            unsigned i11 = (by1 && bx1) ? (unsigned)((y0 + 1) * 14 + x0i + 1) : 0u;
            sbuf[(k * 4 + 0) * 196 + t] = c00;
            sbuf[(k * 4 + 1) * 196 + t] = c01;
            sbuf[(k * 4 + 2) * 196 + t] = c10;
            sbuf[(k * 4 + 3) * 196 + t] = c11;
            sidx[k * 196 + t] = i00 | (i01 << 8) | (i10 << 16) | (i11 << 24);
        }
    }
    __syncthreads();

    // phase 4: per-k shared gather, then 16-channel FFMA2 accumulation
    ull acc[8];
    {
        const ull* bp = (const ull*)(sb2s + g * 16);
#pragma unroll
        for (int j = 0; j < 8; j++) acc[j] = bp[j];
    }
    for (int k = 0; k < 9; k++) {
        unsigned ip = sidx[k * 196 + p];
        float c0 = sbuf[(k * 4 + 0) * 196 + p];
        float c1 = sbuf[(k * 4 + 1) * 196 + p];
        float c2 = sbuf[(k * 4 + 2) * 196 + p];
        float c3 = sbuf[(k * 4 + 3) * 196 + p];
        int i00 = ip & 255, i01 = (ip >> 8) & 255;
        int i10 = (ip >> 16) & 255, i11 = ip >> 24;
#pragma unroll
        for (int j = 0; j < 8; j++) {
            const float* base = sh + (g * 8 + j) * 196;
            sv[(g * 8 + j) * 196 + p] =
                c0 * base[i00] + c1 * base[i01] + c2 * base[i10] + c3 * base[i11];
        }
        __syncthreads();
        const float* wk = sw2 + k * 2048 + g * 16;
#pragma unroll 4
        for (int c = 0; c < 32; c++) {
            ull vs = splat2(sv[c * 196 + p]);
            const ulonglong2* wp = (const ulonglong2*)(wk + c * 64);
            ulonglong2 wa = wp[0], wb = wp[1], wc = wp[2], wd = wp[3];
            acc[0] = ffma2(vs, wa.x, acc[0]); acc[1] = ffma2(vs, wa.y, acc[1]);
            acc[2] = ffma2(vs, wb.x, acc[2]); acc[3] = ffma2(vs, wb.y, acc[3]);
            acc[4] = ffma2(vs, wc.x, acc[4]); acc[5] = ffma2(vs, wc.y, acc[5]);
            acc[6] = ffma2(vs, wd.x, acc[6]); acc[7] = ffma2(vs, wd.y, acc[7]);
        }
        __syncthreads();
    }
#pragma unroll
    for (int j = 0; j < 8; j++) {
        float2 u = f2unpack(acc[j]);
        g_h2[(b * 64 + g * 16 + 2 * j    ) * 196 + p] = fmaxf(u.x, 0.0f);
        g_h2[(b * 64 + g * 16 + 2 * j + 1) * 196 + p] = fmaxf(u.y, 0.0f);
    }
}

// ---------------- FC1: split-K GEMM (M=1024, N=128, K=12544) ---------------
// BM=32, BN=128, BK=16, splitK=16, 256 threads/block, thread tile 4x4 (FFMA2).
__global__ __launch_bounds__(256) void kC_gemm() {
    __shared__ __align__(16) float As[16][32];
    __shared__ __align__(16) float Bs[16][128];
    int tid = threadIdx.x;
    int m0 = blockIdx.x * 32;
    int z  = blockIdx.z;
    int kbase = z * 784;

    ull acc[4][2];
#pragma unroll
    for (int i = 0; i < 4; i++) { acc[i][0] = 0ull; acc[i][1] = 0ull; }

    int lm = tid / 8;            // A load: row within tile
    int lk = (tid % 8) * 2;      // A load: k pair
    int br = tid / 32;           // B load: row 0..7 (and +8)
    int bc = (tid % 32) * 4;     // B load: col quad
    int m_base = (tid >> 5) * 4;
    int n_base = (tid & 31) * 4;

    for (int it = 0; it < 49; it++) {
        int k0 = kbase + it * 16;
        const float* arow = g_h2 + (m0 + lm) * 12544 + k0 + lk;
        float a0 = arow[0], a1 = arow[1];
        As[lk][lm] = a0; As[lk + 1][lm] = a1;
        float4 b0 = *reinterpret_cast<const float4*>(&g_fw1T[(k0 + br) * 128 + bc]);
        float4 b1 = *reinterpret_cast<const float4*>(&g_fw1T[(k0 + br + 8) * 128 + bc]);
        *reinterpret_cast<float4*>(&Bs[br][bc]) = b0;
        *reinterpret_cast<float4*>(&Bs[br + 8][bc]) = b1;
        __syncthreads();
#pragma unroll
        for (int k = 0; k < 16; k++) {
            float4 av = *reinterpret_cast<const float4*>(&As[k][m_base]);
            ulonglong2 bv = *reinterpret_cast<const ulonglong2*>(&Bs[k][n_base]);
            ull s;
            s = splat2(av.x); acc[0][0] = ffma2(s, bv.x, acc[0][0]); acc[0][1] = ffma2(s, bv.y, acc[0][1]);
            s = splat2(av.y); acc[1][0] = ffma2(s, bv.x, acc[1][0]); acc[1][1] = ffma2(s, bv.y, acc[1][1]);
            s = splat2(av.z); acc[2][0] = ffma2(s, bv.x, acc[2][0]); acc[2][1] = ffma2(s, bv.y, acc[2][1]);
            s = splat2(av.w); acc[3][0] = ffma2(s, bv.x, acc[3][0]); acc[3][1] = ffma2(s, bv.y, acc[3][1]);
        }
        __syncthreads();
    }
#pragma unroll
    for (int i = 0; i < 4; i++) {
        float2 u0 = f2unpack(acc[i][0]);
        float2 u1 = f2unpack(acc[i][1]);
        float* dst = g_fc1part + z * 131072 + (m0 + m_base + i) * 128 + n_base;
        dst[0] = u0.x; dst[1] = u0.y; dst[2] = u1.x; dst[3] = u1.y;
    }
}

__global__ void kE_reduce(const float* __restrict__ fb1) {
    int id = blockIdx.x * blockDim.x + threadIdx.x;  // 131072
    if (id >= 131072) return;
    int n = id % 128;
    float s = fb1[n];
#pragma unroll
    for (int zz = 0; zz < 16; zz++) s += g_fc1part[zz * 131072 + id];
    g_h3[id] = fmaxf(s, 0.0f);
}

// ---------------- FC2 ------------------------------------------------------
__global__ void kF_fc2(const float* __restrict__ fw2, const float* __restrict__ fb2,
                       float* __restrict__ out) {
    int id = blockIdx.x * blockDim.x + threadIdx.x;  // 10240
    if (id >= 10240) return;
    int m = id / 10, n = id % 10;
    float s = fb2[n];
    const float* hrow = g_h3 + m * 128;
    const float* wrow = fw2 + n * 128;
#pragma unroll 8
    for (int j = 0; j < 128; j++) s += hrow[j] * wrow[j];
    out[id] = s;
}

// ---------------- launch ---------------------------------------------------
extern "C" void kernel_launch(void* const* d_in, const int* in_sizes, int n_in,
                              void* d_out, int out_size) {
    const float* x   = (const float*)d_in[0];
    const float* ow1 = (const float*)d_in[1];
    const float* ob1 = (const float*)d_in[2];
    const float* w1  = (const float*)d_in[3];
    const float* b1  = (const float*)d_in[4];
    const float* ow2 = (const float*)d_in[5];
    const float* ob2 = (const float*)d_in[6];
    const float* w2  = (const float*)d_in[7];
    const float* b2  = (const float*)d_in[8];
    const float* fw1 = (const float*)d_in[9];
    const float* fb1 = (const float*)d_in[10];
    const float* fw2 = (const float*)d_in[11];
    const float* fb2 = (const float*)d_in[12];
    float* out = (float*)d_out;

    prep_w2r <<<(18432 + 255) / 256, 256>>>(w2);
    prep_ow2r<<<(5760  + 255) / 256, 256>>>(ow2);
    prep_fw1T<<<(12544 * 128 + 255) / 256, 256>>>(fw1);

    kA<<<1024, 784>>>(x, ow1, ob1, w1, b1);

    const int KB_SMEM = 45088 * 4;   // 180352 bytes
    cudaFuncSetAttribute(kB, cudaFuncAttributeMaxDynamicSharedMemorySize, KB_SMEM);
    kB<<<1024, 784, KB_SMEM>>>(ob2, b2);

    dim3 gg(32, 1, 16);
    kC_gemm<<<gg, 256>>>();
    kE_reduce<<<(131072 + 255) / 256, 256>>>(fb1);
    kF_fc2<<<(10240 + 255) / 256, 256>>>(fw2, fb2, out);
}